// round 1
// baseline (speedup 1.0000x reference)
#include <cuda_runtime.h>

// Problem constants (fixed by the dataset)
#define NN      12288
#define IND     16
#define HID     256
#define NC      16
#define STRIDE  192     // per-column edge capacity; deg ~ Binom(N, 64/N): mean 64, std 8 -> 192 is >15 sigma
#define BN1     8       // nodes per block in k_y1
#define BN2     16      // nodes per block in k_y2 / k_agg2

// ---- scratch (static device allocations; no cudaMalloc allowed) ----
__device__ int   g_cnt[NN];               // per-column nonzero count of A (excl. self loop)
__device__ int   g_rows[NN * STRIDE];     // per-column row-index lists (CSC-ish, fixed stride)
__device__ float g_dis[NN];               // deg^{-1/2}, deg = cnt + 1
__device__ float g_y1[NN * HID];          // dis * (x @ W1)
__device__ float g_h1[NN * HID];          // relu(layer-1 output)
__device__ float g_y2[NN * NC];           // dis * (h1 @ W2)
__device__ float g_cmax[NC];
__device__ float g_csum[NC];

// ---- 0: reset per-column counters (graph replays reuse device globals) ----
__global__ void k_zero() {
    int t = blockIdx.x * blockDim.x + threadIdx.x;
    if (t < NN) g_cnt[t] = 0;
}

// ---- 1: one streaming pass over A: extract structure + per-column counts ----
// block = one row i; threads stream float4 over columns (coalesced).
__global__ void k_extract(const float* __restrict__ A) {
    int i = blockIdx.x;
    const float4* row = (const float4*)(A + (size_t)i * NN);
    for (int t = threadIdx.x; t < NN / 4; t += blockDim.x) {
        float4 v = row[t];
        int j = t * 4;
        if (v.x != 0.0f) { int p = atomicAdd(&g_cnt[j + 0], 1); if (p < STRIDE) g_rows[(j + 0) * STRIDE + p] = i; }
        if (v.y != 0.0f) { int p = atomicAdd(&g_cnt[j + 1], 1); if (p < STRIDE) g_rows[(j + 1) * STRIDE + p] = i; }
        if (v.z != 0.0f) { int p = atomicAdd(&g_cnt[j + 2], 1); if (p < STRIDE) g_rows[(j + 2) * STRIDE + p] = i; }
        if (v.w != 0.0f) { int p = atomicAdd(&g_cnt[j + 3], 1); if (p < STRIDE) g_rows[(j + 3) * STRIDE + p] = i; }
    }
}

// ---- 2: dis = rsqrt(deg), deg = column nnz + 1 (self loop; A[j,j]=1 already counted) ----
__global__ void k_dis() {
    int t = blockIdx.x * blockDim.x + threadIdx.x;
    if (t < NN) g_dis[t] = rsqrtf((float)(g_cnt[t] + 1));
}

// ---- 3: y1 = dis .* (x @ W1)   [N x 256] ----
// block handles BN1 nodes; thread c keeps its W1 column (16 regs), reuses across nodes.
__global__ void k_y1(const float* __restrict__ x, const float* __restrict__ W1) {
    int jb = blockIdx.x * BN1;
    int c  = threadIdx.x;           // 0..255
    float w[IND];
    #pragma unroll
    for (int k = 0; k < IND; k++) w[k] = W1[k * HID + c];
    __shared__ float xs[BN1 * IND];
    if (threadIdx.x < BN1 * IND) xs[threadIdx.x] = x[jb * IND + threadIdx.x];
    __syncthreads();
    #pragma unroll
    for (int n = 0; n < BN1; n++) {
        float acc = 0.0f;
        #pragma unroll
        for (int k = 0; k < IND; k++) acc += xs[n * IND + k] * w[k];
        g_y1[(jb + n) * HID + c] = g_dis[jb + n] * acc;
    }
}

// ---- 4: layer-1 aggregation + bias + relu ----
// block = one destination node j; thread c = one channel. Index list staged in SMEM,
// 4 accumulators -> 4 independent L2 loads in flight.
__global__ void k_agg1(const float* __restrict__ b1) {
    int j = blockIdx.x;
    int c = threadIdx.x;
    __shared__ int sl[STRIDE];
    int d = min(g_cnt[j], STRIDE);
    for (int e = threadIdx.x; e < d; e += blockDim.x) sl[e] = g_rows[j * STRIDE + e];
    __syncthreads();
    float a0 = g_y1[j * HID + c];   // explicit self-loop term (the +I)
    float a1 = 0.0f, a2 = 0.0f, a3 = 0.0f;
    int e = 0;
    for (; e + 4 <= d; e += 4) {
        int i0 = sl[e], i1 = sl[e + 1], i2 = sl[e + 2], i3 = sl[e + 3];
        a0 += g_y1[i0 * HID + c];
        a1 += g_y1[i1 * HID + c];
        a2 += g_y1[i2 * HID + c];
        a3 += g_y1[i3 * HID + c];
    }
    for (; e < d; e++) a0 += g_y1[sl[e] * HID + c];
    float r = g_dis[j] * ((a0 + a1) + (a2 + a3)) + b1[c];
    g_h1[j * HID + c] = fmaxf(r, 0.0f);
}

// ---- 5: y2 = dis .* (h1 @ W2)   [N x 16] ----
// block handles BN2 nodes. h1 tile + W2 staged in SMEM (padded to kill bank conflicts).
__global__ void k_y2(const float* __restrict__ W2) {
    __shared__ float w2s[HID * NC];          // 16 KB
    __shared__ float sh[BN2][HID + 1];       // ~16.4 KB, pad=1 -> conflict-free
    int jb = blockIdx.x * BN2;
    for (int t = threadIdx.x; t < HID * NC; t += blockDim.x) w2s[t] = W2[t];
    for (int t = threadIdx.x; t < BN2 * HID; t += blockDim.x) {
        int n = t / HID, k = t % HID;
        sh[n][k] = g_h1[(jb + n) * HID + k];
    }
    __syncthreads();
    int n = threadIdx.x / NC, c = threadIdx.x % NC;
    float acc = 0.0f;
    #pragma unroll 8
    for (int k = 0; k < HID; k++) acc += sh[n][k] * w2s[k * NC + c];
    int j = jb + n;
    g_y2[j * NC + c] = g_dis[j] * acc;
}

// ---- 6: layer-2 aggregation + bias + skip(x); writes logits to d_out ----
__global__ void k_agg2(const float* __restrict__ x, const float* __restrict__ b2,
                       float* __restrict__ out) {
    int jb = blockIdx.x * BN2;
    __shared__ int sl[BN2][STRIDE];          // 12 KB
    __shared__ int sdd[BN2];
    for (int t = threadIdx.x; t < BN2 * STRIDE; t += blockDim.x)
        ((int*)sl)[t] = g_rows[jb * STRIDE + t];
    if (threadIdx.x < BN2) sdd[threadIdx.x] = min(g_cnt[jb + threadIdx.x], STRIDE);
    __syncthreads();
    int n = threadIdx.x / NC, c = threadIdx.x % NC;
    int j = jb + n;
    int d = sdd[n];
    float a0 = g_y2[j * NC + c];             // self loop
    float a1 = 0.0f;
    int e = 0;
    for (; e + 2 <= d; e += 2) {
        a0 += g_y2[sl[n][e]     * NC + c];
        a1 += g_y2[sl[n][e + 1] * NC + c];
    }
    if (e < d) a0 += g_y2[sl[n][e] * NC + c];
    out[j * NC + c] = g_dis[j] * (a0 + a1) + b2[c] + x[j * NC + c];
}

// ---- 7: per-class (axis=0) max and sum(exp) ----
__global__ void k_colreduce(const float* __restrict__ out) {
    int c = blockIdx.x;                      // 16 blocks
    __shared__ float red[256];
    float m = -1e30f;
    for (int j = threadIdx.x; j < NN; j += 256) m = fmaxf(m, out[j * NC + c]);
    red[threadIdx.x] = m; __syncthreads();
    for (int s = 128; s > 0; s >>= 1) {
        if (threadIdx.x < s) red[threadIdx.x] = fmaxf(red[threadIdx.x], red[threadIdx.x + s]);
        __syncthreads();
    }
    m = red[0]; __syncthreads();
    float s = 0.0f;
    for (int j = threadIdx.x; j < NN; j += 256) s += expf(out[j * NC + c] - m);
    red[threadIdx.x] = s; __syncthreads();
    for (int st = 128; st > 0; st >>= 1) {
        if (threadIdx.x < st) red[threadIdx.x] += red[threadIdx.x + st];
        __syncthreads();
    }
    if (threadIdx.x == 0) { g_cmax[c] = m; g_csum[c] = red[0]; }
}

// ---- 8: normalize in place ----
__global__ void k_softmax(float* __restrict__ out) {
    int t = blockIdx.x * blockDim.x + threadIdx.x;
    if (t < NN * NC) {
        int c = t & (NC - 1);
        out[t] = expf(out[t] - g_cmax[c]) / g_csum[c];
    }
}

extern "C" void kernel_launch(void* const* d_in, const int* in_sizes, int n_in,
                              void* d_out, int out_size) {
    const float* A  = (const float*)d_in[0];
    const float* x  = (const float*)d_in[1];
    const float* W1 = (const float*)d_in[2];
    const float* b1 = (const float*)d_in[3];
    const float* W2 = (const float*)d_in[4];
    const float* b2 = (const float*)d_in[5];
    float* out = (float*)d_out;

    k_zero<<<(NN + 255) / 256, 256>>>();
    k_extract<<<NN, 256>>>(A);
    k_dis<<<(NN + 255) / 256, 256>>>();
    k_y1<<<NN / BN1, HID>>>(x, W1);
    k_agg1<<<NN, HID>>>(b1);
    k_y2<<<NN / BN2, 256>>>(W2);
    k_agg2<<<NN / BN2, 256>>>(x, b2, out);
    k_colreduce<<<NC, 256>>>(out);
    k_softmax<<<(NN * NC + 255) / 256, 256>>>(out);
}

// round 2
// speedup vs baseline: 1.2469x; 1.2469x over previous
#include <cuda_runtime.h>

// Problem constants (fixed by the dataset)
#define NN      12288
#define IND     16
#define HID     256
#define NC      16
#define STRIDE  192     // per-column capacity; deg ~ Binom(N, 64/N) -> 192 is >15 sigma
#define BNH     16      // nodes per block in fused h1y2
#define NPBA    32      // nodes per block in aggregation kernels

// ---- scratch (static device arrays; no cudaMalloc allowed) ----
__device__ int   g_cnt[NN];               // per-column nnz of A (self entry included if present)
__device__ int   g_rows[NN * STRIDE];     // per-column row lists (CSC-ish, fixed stride)
__device__ float g_dis[NN];               // deg^{-1/2}, deg = cnt + 1
__device__ float g_dx[NN * IND];          // dis[i] * x[i]  (16-dim)
__device__ float g_s[NN * IND];           // dis_j * sum_col_j dis_i x_i   (pre-transform agg)
__device__ float g_y2[NN * NC];           // dis * (h1 @ W2)
__device__ float g_cmax[NC];
__device__ float g_csum[NC];

// ---- 0: reset counters (graph replays reuse device globals) ----
__global__ void k_zero() {
    int t = blockIdx.x * blockDim.x + threadIdx.x;
    if (t < NN) g_cnt[t] = 0;
}

// ---- 1: single streaming pass over A: structure + per-column counts ----
__global__ void k_extract(const float* __restrict__ A) {
    int i = blockIdx.x;
    const float4* row = (const float4*)(A + (size_t)i * NN);
    for (int t = threadIdx.x; t < NN / 4; t += blockDim.x) {
        float4 v = row[t];
        int j = t * 4;
        if (v.x != 0.0f) { int p = atomicAdd(&g_cnt[j + 0], 1); if (p < STRIDE) g_rows[(j + 0) * STRIDE + p] = i; }
        if (v.y != 0.0f) { int p = atomicAdd(&g_cnt[j + 1], 1); if (p < STRIDE) g_rows[(j + 1) * STRIDE + p] = i; }
        if (v.z != 0.0f) { int p = atomicAdd(&g_cnt[j + 2], 1); if (p < STRIDE) g_rows[(j + 2) * STRIDE + p] = i; }
        if (v.w != 0.0f) { int p = atomicAdd(&g_cnt[j + 3], 1); if (p < STRIDE) g_rows[(j + 3) * STRIDE + p] = i; }
    }
}

// ---- 2: dis = rsqrt(cnt+1); dx = dis * x ----
__global__ void k_prep(const float* __restrict__ x) {
    int t = blockIdx.x * blockDim.x + threadIdx.x;
    if (t >= NN) return;
    float dis = rsqrtf((float)(g_cnt[t] + 1));
    g_dis[t] = dis;
    const float4* xr = (const float4*)(x + t * IND);
    float4* dr = (float4*)(g_dx + t * IND);
    #pragma unroll
    for (int q = 0; q < 4; q++) {
        float4 v = xr[q];
        v.x *= dis; v.y *= dis; v.z *= dis; v.w *= dis;
        dr[q] = v;
    }
}

// ---- 3: input-space aggregation: s[j] = dis_j * (dx[j] + sum_{i in col j} dx[i]) ----
// 4 threads per node, float4 lanes; edge lists staged in SMEM; 2 accumulators.
__global__ void k_xagg() {
    __shared__ int sl[NPBA][STRIDE];   // 24 KB
    __shared__ int sdd[NPBA];
    int jb = blockIdx.x * NPBA;
    for (int t = threadIdx.x; t < NPBA * STRIDE; t += blockDim.x)
        ((int*)sl)[t] = g_rows[jb * STRIDE + t];
    if (threadIdx.x < NPBA) sdd[threadIdx.x] = min(g_cnt[jb + threadIdx.x], STRIDE);
    __syncthreads();
    int n = threadIdx.x >> 2, q = threadIdx.x & 3;
    int j = jb + n;
    int d = sdd[n];
    float4 a0 = *(const float4*)(g_dx + j * IND + q * 4);   // explicit self loop (+I)
    float4 a1 = make_float4(0.f, 0.f, 0.f, 0.f);
    int e = 0;
    for (; e + 2 <= d; e += 2) {
        const float4 v0 = *(const float4*)(g_dx + sl[n][e]     * IND + q * 4);
        const float4 v1 = *(const float4*)(g_dx + sl[n][e + 1] * IND + q * 4);
        a0.x += v0.x; a0.y += v0.y; a0.z += v0.z; a0.w += v0.w;
        a1.x += v1.x; a1.y += v1.y; a1.z += v1.z; a1.w += v1.w;
    }
    if (e < d) {
        const float4 v0 = *(const float4*)(g_dx + sl[n][e] * IND + q * 4);
        a0.x += v0.x; a0.y += v0.y; a0.z += v0.z; a0.w += v0.w;
    }
    float dj = g_dis[j];
    float4 r;
    r.x = dj * (a0.x + a1.x); r.y = dj * (a0.y + a1.y);
    r.z = dj * (a0.z + a1.z); r.w = dj * (a0.w + a1.w);
    *(float4*)(g_s + j * IND + q * 4) = r;
}

// ---- 4: fused per-node MLP: y2 = dis .* (relu(s@W1 + b1) @ W2), h1 never hits HBM ----
__global__ void k_h1y2(const float* __restrict__ W1, const float* __restrict__ b1,
                       const float* __restrict__ W2) {
    __shared__ float ss[BNH][IND];        // 1 KB
    __shared__ float sh[BNH][HID + 1];    // 16.4 KB, pad kills phase-2 conflicts
    int jb = blockIdx.x * BNH;
    if (threadIdx.x < BNH * IND) ((float*)ss)[threadIdx.x] = g_s[jb * IND + threadIdx.x];
    __syncthreads();
    int c = threadIdx.x;                  // 0..255
    float w[IND];
    #pragma unroll
    for (int k = 0; k < IND; k++) w[k] = __ldg(&W1[k * HID + c]);
    float bb = __ldg(&b1[c]);
    #pragma unroll
    for (int n = 0; n < BNH; n++) {
        float acc = bb;
        #pragma unroll
        for (int k = 0; k < IND; k++) acc += ss[n][k] * w[k];
        sh[n][c] = fmaxf(acc, 0.0f);
    }
    __syncthreads();
    int n = threadIdx.x / NC, cc = threadIdx.x % NC;
    float acc = 0.0f;
    #pragma unroll 8
    for (int k = 0; k < HID; k++) acc += sh[n][k] * __ldg(&W2[k * NC + cc]);
    int j = jb + n;
    g_y2[j * NC + cc] = g_dis[j] * acc;
}

// ---- 5: layer-2 aggregation + bias + skip(x); writes logits to d_out ----
__global__ void k_agg2(const float* __restrict__ x, const float* __restrict__ b2,
                       float* __restrict__ out) {
    __shared__ int sl[NPBA][STRIDE];
    __shared__ int sdd[NPBA];
    int jb = blockIdx.x * NPBA;
    for (int t = threadIdx.x; t < NPBA * STRIDE; t += blockDim.x)
        ((int*)sl)[t] = g_rows[jb * STRIDE + t];
    if (threadIdx.x < NPBA) sdd[threadIdx.x] = min(g_cnt[jb + threadIdx.x], STRIDE);
    __syncthreads();
    int n = threadIdx.x >> 2, q = threadIdx.x & 3;
    int j = jb + n;
    int d = sdd[n];
    float4 a0 = *(const float4*)(g_y2 + j * NC + q * 4);    // self loop
    float4 a1 = make_float4(0.f, 0.f, 0.f, 0.f);
    int e = 0;
    for (; e + 2 <= d; e += 2) {
        const float4 v0 = *(const float4*)(g_y2 + sl[n][e]     * NC + q * 4);
        const float4 v1 = *(const float4*)(g_y2 + sl[n][e + 1] * NC + q * 4);
        a0.x += v0.x; a0.y += v0.y; a0.z += v0.z; a0.w += v0.w;
        a1.x += v1.x; a1.y += v1.y; a1.z += v1.z; a1.w += v1.w;
    }
    if (e < d) {
        const float4 v0 = *(const float4*)(g_y2 + sl[n][e] * NC + q * 4);
        a0.x += v0.x; a0.y += v0.y; a0.z += v0.z; a0.w += v0.w;
    }
    float dj = g_dis[j];
    const float4 xb = *(const float4*)(x + j * IND + q * 4);
    const float4 bb = *(const float4*)(b2 + q * 4);
    float4 r;
    r.x = dj * (a0.x + a1.x) + bb.x + xb.x;
    r.y = dj * (a0.y + a1.y) + bb.y + xb.y;
    r.z = dj * (a0.z + a1.z) + bb.z + xb.z;
    r.w = dj * (a0.w + a1.w) + bb.w + xb.w;
    *(float4*)(out + j * NC + q * 4) = r;
}

// ---- 6: per-class (axis=0) max and sum(exp) ----
__global__ void k_colreduce(const float* __restrict__ out) {
    int c = blockIdx.x;                      // 16 blocks
    __shared__ float red[256];
    float m = -1e30f;
    for (int j = threadIdx.x; j < NN; j += 256) m = fmaxf(m, out[j * NC + c]);
    red[threadIdx.x] = m; __syncthreads();
    for (int s = 128; s > 0; s >>= 1) {
        if (threadIdx.x < s) red[threadIdx.x] = fmaxf(red[threadIdx.x], red[threadIdx.x + s]);
        __syncthreads();
    }
    m = red[0]; __syncthreads();
    float s = 0.0f;
    for (int j = threadIdx.x; j < NN; j += 256) s += expf(out[j * NC + c] - m);
    red[threadIdx.x] = s; __syncthreads();
    for (int st = 128; st > 0; st >>= 1) {
        if (threadIdx.x < st) red[threadIdx.x] += red[threadIdx.x + st];
        __syncthreads();
    }
    if (threadIdx.x == 0) { g_cmax[c] = m; g_csum[c] = red[0]; }
}

// ---- 7: normalize in place ----
__global__ void k_softmax(float* __restrict__ out) {
    int t = blockIdx.x * blockDim.x + threadIdx.x;
    if (t < NN * NC) {
        int c = t & (NC - 1);
        out[t] = expf(out[t] - g_cmax[c]) / g_csum[c];
    }
}

extern "C" void kernel_launch(void* const* d_in, const int* in_sizes, int n_in,
                              void* d_out, int out_size) {
    const float* A  = (const float*)d_in[0];
    const float* x  = (const float*)d_in[1];
    const float* W1 = (const float*)d_in[2];
    const float* b1 = (const float*)d_in[3];
    const float* W2 = (const float*)d_in[4];
    const float* b2 = (const float*)d_in[5];
    float* out = (float*)d_out;

    k_zero<<<(NN + 255) / 256, 256>>>();
    k_extract<<<NN, 256>>>(A);
    k_prep<<<(NN + 255) / 256, 256>>>(x);
    k_xagg<<<NN / NPBA, 128>>>();
    k_h1y2<<<NN / BNH, HID>>>(W1, b1, W2);
    k_agg2<<<NN / NPBA, 128>>>(x, b2, out);
    k_colreduce<<<NC, 256>>>(out);
    k_softmax<<<(NN * NC + 255) / 256, 256>>>(out);
}

// round 3
// speedup vs baseline: 1.2617x; 1.0119x over previous
#include <cuda_runtime.h>

// Problem constants (fixed by the dataset)
#define NN      12288
#define IND     16
#define HID     256
#define NC      16
#define STRIDE  192     // per-column capacity; deg ~ Binom(N, 64/N) -> >15 sigma
#define BNH     16      // nodes per block in fused h1y2
#define NPBA    16      // nodes per block in aggregation kernels (16 threads/node)

// ---- scratch (static device arrays; no cudaMalloc allowed) ----
__device__ int   g_cnt[NN];
__device__ int   g_rows[NN * STRIDE];
__device__ float g_dis[NN];
__device__ float g_dx[NN * IND];          // dis[i] * x[i]
__device__ float g_s[NN * IND];           // aggregated pre-transform features
__device__ float g_y2[NN * NC];
__device__ float g_cmax[NC];
__device__ float g_csum[NC];

// ---- 0: reset counters ----
__global__ void k_zero() {
    int t = blockIdx.x * blockDim.x + threadIdx.x;
    if (t < NN) g_cnt[t] = 0;
}

// ---- 1: single streaming pass over A: structure + per-column counts ----
__global__ void k_extract(const float* __restrict__ A) {
    int i = blockIdx.x;
    const float4* row = (const float4*)(A + (size_t)i * NN);
    for (int t = threadIdx.x; t < NN / 4; t += blockDim.x) {
        float4 v = __ldcs(&row[t]);       // streaming: don't thrash L2
        int j = t * 4;
        if (v.x != 0.0f) { int p = atomicAdd(&g_cnt[j + 0], 1); if (p < STRIDE) g_rows[(j + 0) * STRIDE + p] = i; }
        if (v.y != 0.0f) { int p = atomicAdd(&g_cnt[j + 1], 1); if (p < STRIDE) g_rows[(j + 1) * STRIDE + p] = i; }
        if (v.z != 0.0f) { int p = atomicAdd(&g_cnt[j + 2], 1); if (p < STRIDE) g_rows[(j + 2) * STRIDE + p] = i; }
        if (v.w != 0.0f) { int p = atomicAdd(&g_cnt[j + 3], 1); if (p < STRIDE) g_rows[(j + 3) * STRIDE + p] = i; }
    }
}

// ---- 2: dis = rsqrt(cnt+1); dx = dis * x ----
__global__ void k_prep(const float* __restrict__ x) {
    int t = blockIdx.x * blockDim.x + threadIdx.x;
    if (t >= NN) return;
    float dis = rsqrtf((float)(g_cnt[t] + 1));
    g_dis[t] = dis;
    const float4* xr = (const float4*)(x + t * IND);
    float4* dr = (float4*)(g_dx + t * IND);
    #pragma unroll
    for (int q = 0; q < 4; q++) {
        float4 v = xr[q];
        v.x *= dis; v.y *= dis; v.z *= dis; v.w *= dis;
        dr[q] = v;
    }
}

// ---- helpers for the split-edge gather ----
__device__ __forceinline__ void f4add(float4& a, const float4& v) {
    a.x += v.x; a.y += v.y; a.z += v.z; a.w += v.w;
}
__device__ __forceinline__ float4 f4red(float4 a0, const float4& a1) {
    f4add(a0, a1);
    a0.x += __shfl_xor_sync(0xffffffffu, a0.x, 4);
    a0.y += __shfl_xor_sync(0xffffffffu, a0.y, 4);
    a0.z += __shfl_xor_sync(0xffffffffu, a0.z, 4);
    a0.w += __shfl_xor_sync(0xffffffffu, a0.w, 4);
    a0.x += __shfl_xor_sync(0xffffffffu, a0.x, 8);
    a0.y += __shfl_xor_sync(0xffffffffu, a0.y, 8);
    a0.z += __shfl_xor_sync(0xffffffffu, a0.z, 8);
    a0.w += __shfl_xor_sync(0xffffffffu, a0.w, 8);
    return a0;
}

// ---- 3: input-space aggregation: s[j] = dis_j * (dx[j] + sum_{i in col j} dx[i]) ----
// 16 threads/node: 4 float4 lanes x 4 edge-splits, 2 accumulators each -> MLP=8/node.
__global__ void k_xagg() {
    __shared__ int sl[NPBA][STRIDE];   // 12 KB
    __shared__ int sdd[NPBA];
    int jb = blockIdx.x * NPBA;
    for (int t = threadIdx.x; t < NPBA * STRIDE; t += blockDim.x)
        ((int*)sl)[t] = g_rows[jb * STRIDE + t];
    if (threadIdx.x < NPBA) sdd[threadIdx.x] = min(g_cnt[jb + threadIdx.x], STRIDE);
    __syncthreads();
    int n = threadIdx.x >> 4;            // node in block
    int r = (threadIdx.x >> 2) & 3;      // edge split
    int q = threadIdx.x & 3;             // float4 lane
    int j = jb + n;
    int d = sdd[n];
    float4 a0 = make_float4(0.f, 0.f, 0.f, 0.f), a1 = a0;
    if (r == 0) a0 = *(const float4*)(g_dx + j * IND + q * 4);   // self loop (+I)
    int e = r;
    for (; e + 4 < d; e += 8) {
        const float4 v0 = *(const float4*)(g_dx + sl[n][e]     * IND + q * 4);
        const float4 v1 = *(const float4*)(g_dx + sl[n][e + 4] * IND + q * 4);
        f4add(a0, v0); f4add(a1, v1);
    }
    if (e < d) f4add(a0, *(const float4*)(g_dx + sl[n][e] * IND + q * 4));
    float4 s = f4red(a0, a1);
    if (r == 0) {
        float dj = g_dis[j];
        s.x *= dj; s.y *= dj; s.z *= dj; s.w *= dj;
        *(float4*)(g_s + j * IND + q * 4) = s;
    }
}

// ---- 4: fused per-node MLP: y2 = dis .* (relu(s@W1 + b1) @ W2) ----
__global__ void k_h1y2(const float* __restrict__ W1, const float* __restrict__ b1,
                       const float* __restrict__ W2) {
    __shared__ float ss[BNH][IND];
    __shared__ float sh[BNH][HID + 1];
    int jb = blockIdx.x * BNH;
    if (threadIdx.x < BNH * IND) ((float*)ss)[threadIdx.x] = g_s[jb * IND + threadIdx.x];
    __syncthreads();
    int c = threadIdx.x;
    float w[IND];
    #pragma unroll
    for (int k = 0; k < IND; k++) w[k] = __ldg(&W1[k * HID + c]);
    float bb = __ldg(&b1[c]);
    #pragma unroll
    for (int n = 0; n < BNH; n++) {
        float acc = bb;
        #pragma unroll
        for (int k = 0; k < IND; k++) acc += ss[n][k] * w[k];
        sh[n][c] = fmaxf(acc, 0.0f);
    }
    __syncthreads();
    int n = threadIdx.x / NC, cc = threadIdx.x % NC;
    float acc = 0.0f;
    #pragma unroll 8
    for (int k = 0; k < HID; k++) acc += sh[n][k] * __ldg(&W2[k * NC + cc]);
    int j = jb + n;
    g_y2[j * NC + cc] = g_dis[j] * acc;
}

// ---- 5: layer-2 aggregation + bias + skip(x) -> logits in d_out ----
__global__ void k_agg2(const float* __restrict__ x, const float* __restrict__ b2,
                       float* __restrict__ out) {
    __shared__ int sl[NPBA][STRIDE];
    __shared__ int sdd[NPBA];
    int jb = blockIdx.x * NPBA;
    for (int t = threadIdx.x; t < NPBA * STRIDE; t += blockDim.x)
        ((int*)sl)[t] = g_rows[jb * STRIDE + t];
    if (threadIdx.x < NPBA) sdd[threadIdx.x] = min(g_cnt[jb + threadIdx.x], STRIDE);
    __syncthreads();
    int n = threadIdx.x >> 4;
    int r = (threadIdx.x >> 2) & 3;
    int q = threadIdx.x & 3;
    int j = jb + n;
    int d = sdd[n];
    float4 a0 = make_float4(0.f, 0.f, 0.f, 0.f), a1 = a0;
    if (r == 0) a0 = *(const float4*)(g_y2 + j * NC + q * 4);    // self loop
    int e = r;
    for (; e + 4 < d; e += 8) {
        const float4 v0 = *(const float4*)(g_y2 + sl[n][e]     * NC + q * 4);
        const float4 v1 = *(const float4*)(g_y2 + sl[n][e + 4] * NC + q * 4);
        f4add(a0, v0); f4add(a1, v1);
    }
    if (e < d) f4add(a0, *(const float4*)(g_y2 + sl[n][e] * NC + q * 4));
    float4 s = f4red(a0, a1);
    if (r == 0) {
        float dj = g_dis[j];
        const float4 xb = *(const float4*)(x + j * IND + q * 4);
        const float4 bb = *(const float4*)(b2 + q * 4);
        float4 rr;
        rr.x = dj * s.x + bb.x + xb.x;
        rr.y = dj * s.y + bb.y + xb.y;
        rr.z = dj * s.z + bb.z + xb.z;
        rr.w = dj * s.w + bb.w + xb.w;
        *(float4*)(out + j * NC + q * 4) = rr;
    }
}

// ---- 6: per-class (axis=0) max and sum(exp) ----
__global__ void k_colreduce(const float* __restrict__ out) {
    int c = blockIdx.x;
    __shared__ float red[256];
    float m = -1e30f;
    for (int j = threadIdx.x; j < NN; j += 256) m = fmaxf(m, out[j * NC + c]);
    red[threadIdx.x] = m; __syncthreads();
    for (int s = 128; s > 0; s >>= 1) {
        if (threadIdx.x < s) red[threadIdx.x] = fmaxf(red[threadIdx.x], red[threadIdx.x + s]);
        __syncthreads();
    }
    m = red[0]; __syncthreads();
    float s = 0.0f;
    for (int j = threadIdx.x; j < NN; j += 256) s += expf(out[j * NC + c] - m);
    red[threadIdx.x] = s; __syncthreads();
    for (int st = 128; st > 0; st >>= 1) {
        if (threadIdx.x < st) red[threadIdx.x] += red[threadIdx.x + st];
        __syncthreads();
    }
    if (threadIdx.x == 0) { g_cmax[c] = m; g_csum[c] = red[0]; }
}

// ---- 7: normalize in place ----
__global__ void k_softmax(float* __restrict__ out) {
    int t = blockIdx.x * blockDim.x + threadIdx.x;
    if (t < NN * NC) {
        int c = t & (NC - 1);
        out[t] = expf(out[t] - g_cmax[c]) / g_csum[c];
    }
}

extern "C" void kernel_launch(void* const* d_in, const int* in_sizes, int n_in,
                              void* d_out, int out_size) {
    const float* A  = (const float*)d_in[0];
    const float* x  = (const float*)d_in[1];
    const float* W1 = (const float*)d_in[2];
    const float* b1 = (const float*)d_in[3];
    const float* W2 = (const float*)d_in[4];
    const float* b2 = (const float*)d_in[5];
    float* out = (float*)d_out;

    k_zero<<<(NN + 255) / 256, 256>>>();
    k_extract<<<NN, 256>>>(A);
    k_prep<<<(NN + 255) / 256, 256>>>(x);
    k_xagg<<<NN / NPBA, NPBA * 16>>>();
    k_h1y2<<<NN / BNH, HID>>>(W1, b1, W2);
    k_agg2<<<NN / NPBA, NPBA * 16>>>(x, b2, out);
    k_colreduce<<<NC, 256>>>(out);
    k_softmax<<<(NN * NC + 255) / 256, 256>>>(out);
}